// round 2
// baseline (speedup 1.0000x reference)
#include <cuda_runtime.h>
#include <math.h>

#define BB 64
#define NTOK 2304
#define DD 64
#define NHEADS 8
#define TOKENS (BB*NTOK)   // 147456

// ---------------- scratch (device globals; no allocations) ----------------
__device__ float g_xn[TOKENS*DD];
__device__ float g_v[TOKENS*DD];
__device__ float g_logits[BB*NHEADS*NTOK];
__device__ float g_m[BB*NHEADS];
__device__ float g_cls[(size_t)TOKENS*4*DD];
__device__ float g_WL[NHEADS*DD];
__device__ float g_bL[NHEADS];
__device__ float g_vc[DD];
__device__ float g_clslogit[NHEADS];
__device__ float g_G[DD*DD];
__device__ float g_R[DD*DD];
__device__ float g_u[NHEADS*DD];
__device__ float g_cvec[DD];
__device__ float g_P[NHEADS*DD*DD];
__device__ float g_Q[NHEADS*DD*DD];

__device__ __forceinline__ float kscale() { return 0.35355339059327373f; } // 8^-0.5

// ---------------- precompute A ----------------
__global__ void precompA(const float* __restrict__ bqkv,
                         const float* __restrict__ cls_tok,
                         const float* __restrict__ Wwqkv, const float* __restrict__ bwqkv,
                         const float* __restrict__ Wraq, const float* __restrict__ Wrak,
                         const float* __restrict__ Wrao, const float* __restrict__ Wrav,
                         const float* __restrict__ brao,
                         const float* __restrict__ Wout, const float* __restrict__ bout)
{
    __shared__ float scq[192];
    __shared__ float sqc[64];
    int tid = threadIdx.x;
    if (tid < 192) {
        float a = bwqkv[tid];
        for (int d = 0; d < 64; d++) a += Wwqkv[tid*64+d]*cls_tok[d];
        scq[tid] = a;
    }
    __syncthreads();
    if (tid < 64) { sqc[tid] = scq[tid]*kscale(); g_vc[tid] = scq[128+tid]; }
    __syncthreads();
    if (tid < 8) {
        float cl = 0.f, bl = 0.f;
        for (int j = 0; j < 8; j++) {
            cl += sqc[tid*8+j]*scq[64+tid*8+j];
            bl += sqc[tid*8+j]*bwqkv[64+tid*8+j];
        }
        g_clslogit[tid] = cl; g_bL[tid] = bl;
    }
    for (int i = tid; i < 512; i += 256) {
        int h = i>>6, d = i&63;
        float a = 0.f;
        for (int j = 0; j < 8; j++) a += sqc[h*8+j]*Wwqkv[(64+h*8+j)*64+d];
        g_WL[i] = a;
    }
    for (int i = tid; i < 4096; i += 256) {
        int dd = i>>6, g = i&63;
        float a = 0.f;
        for (int e = 0; e < 64; e++) a += Wraq[e*64+dd]*Wrak[e*64+g];
        g_G[i] = a;
    }
    for (int i = tid; i < 4096; i += 256) {
        int a_ = i>>6, g = i&63;
        float sR = 0.f;
        for (int c = 0; c < 64; c++) sR += Wrao[a_*64+c]*Wrav[c*64+g];
        g_R[i] = sR;
    }
    __syncthreads();
    for (int i = tid; i < 512; i += 256) {
        int h = i>>6, g = i&63;
        float su = 0.f;
        for (int dd = 0; dd < 64; dd++) su += bqkv[h*64+dd]*g_G[dd*64+g];
        g_u[i] = su*kscale();
    }
    if (tid < 64) {
        float sc = bout[tid];
        for (int k = 0; k < 512; k++) sc += Wout[tid*512+k]*brao[k&63];
        g_cvec[tid] = sc;
    }
}

// ---------------- precompute B: P_h and Q_h ----------------
__global__ void precompB(const float* __restrict__ Wqkv, const float* __restrict__ Wout)
{
    __shared__ float sM[4096];
    int h = blockIdx.x & 7;
    int which = blockIdx.x >> 3;
    int tid = threadIdx.x;
    const float* src = which ? g_R : g_G;
    for (int i = tid; i < 4096; i += 256) sM[i] = src[i];
    __syncthreads();
    if (which == 0) {
        for (int i = tid; i < 4096; i += 256) {
            int f = i>>6, g = i&63;
            float s = 0.f;
            for (int dd = 0; dd < 64; dd++) s += Wqkv[(h*64+dd)*64 + f]*sM[dd*64+g];
            g_P[h*4096 + i] = s*kscale();
        }
    } else {
        for (int i = tid; i < 4096; i += 256) {
            int g = i>>6, o = i&63;
            float s = 0.f;
            for (int a = 0; a < 64; a++) s += Wout[o*512 + h*64 + a]*sM[a*64+g];
            g_Q[h*4096 + i] = s;
        }
    }
}

// ---------------- K1: LayerNorm + logits + v projection (warp per token) ----------------
__global__ void __launch_bounds__(256) k_ln(const float* __restrict__ x,
     const float* __restrict__ ln_g, const float* __restrict__ ln_b,
     const float* __restrict__ Wwqkv, const float* __restrict__ bwqkv)
{
    __shared__ float swv[64*65];
    __shared__ float sWL[8*65];
    __shared__ float sxb[8*64];
    __shared__ float sbias[64];
    int tid = threadIdx.x, warp = tid>>5, lane = tid&31;
    for (int i = tid; i < 4096; i += 256)
        swv[(i&63)*65 + (i>>6)] = Wwqkv[8192 + i];          // swv[d][e] = Wwv[e][d]
    for (int i = tid; i < 512; i += 256)
        sWL[(i>>6)*65 + (i&63)] = g_WL[i];
    if (tid < 64) sbias[tid] = bwqkv[128+tid];
    __syncthreads();
    int token = blockIdx.x*8 + warp;
    float x0 = x[token*64 + lane];
    float x1 = x[token*64 + lane + 32];
    float s = x0 + x1, ss = x0*x0 + x1*x1;
    #pragma unroll
    for (int off = 16; off; off >>= 1) {
        s  += __shfl_xor_sync(0xffffffffu, s,  off);
        ss += __shfl_xor_sync(0xffffffffu, ss, off);
    }
    float mu = s*(1.f/64.f);
    float var = ss*(1.f/64.f) - mu*mu;
    float rstd = rsqrtf(var + 1e-5f);
    float xn0 = (x0-mu)*rstd*ln_g[lane] + ln_b[lane];
    float xn1 = (x1-mu)*rstd*ln_g[lane+32] + ln_b[lane+32];
    g_xn[token*64+lane] = xn0;
    g_xn[token*64+lane+32] = xn1;
    sxb[warp*64+lane] = xn0; sxb[warp*64+lane+32] = xn1;
    __syncwarp();
    float v0 = sbias[lane], v1 = sbias[lane+32];
    #pragma unroll 8
    for (int d = 0; d < 64; d++) {
        float xd = sxb[warp*64+d];
        v0 += xd*swv[d*65+lane];
        v1 += xd*swv[d*65+lane+32];
    }
    g_v[token*64+lane] = v0;
    g_v[token*64+lane+32] = v1;
    if (lane < 8) {
        float a = g_bL[lane];
        #pragma unroll 8
        for (int d = 0; d < 64; d++) a += sxb[warp*64+d]*sWL[lane*65+d];
        int b = token/NTOK, nn = token - b*NTOK;
        g_logits[(b*8+lane)*NTOK + nn] = a;
    }
}

// ---------------- K2: per-(b,h) max ----------------
__global__ void k_max()
{
    __shared__ float red[256];
    int bid = blockIdx.x, tid = threadIdx.x;
    float m = -1e30f;
    for (int i = tid; i < NTOK; i += 256) m = fmaxf(m, g_logits[bid*NTOK + i]);
    red[tid] = m;
    __syncthreads();
    for (int s = 128; s; s >>= 1) {
        if (tid < s) red[tid] = fmaxf(red[tid], red[tid+s]);
        __syncthreads();
    }
    if (tid == 0) g_m[bid] = fmaxf(red[0], g_clslogit[bid&7]);
}

// ---------------- K3: exp + integral-image quad sums + cls_out ----------------
__global__ void __launch_bounds__(256) k_quad()
{
    extern __shared__ float s[];  // 9 * 2304 floats
    int bid = blockIdx.x, tid = threadIdx.x;
    int b = bid>>3, h = bid&7;
    float m = g_m[bid];
    float ecls = __expf(g_clslogit[h] - m);
    for (int p = tid; p < 2304; p += 256)
        s[p] = __expf(g_logits[bid*NTOK + p] - m);
    __syncthreads();
    for (int i = tid; i < 2304*8; i += 256) {
        int p = i>>3, j = i&7;
        s[(1+j)*2304 + p] = s[p] * g_v[(size_t)(b*NTOK + p)*64 + h*8 + j];
    }
    __syncthreads();
    // row cumsums (9 channels x 48 rows)
    for (int sid = tid; sid < 9*48; sid += 256) {
        int ch = sid/48, y = sid - (sid/48)*48;
        float* row = s + ch*2304 + y*48;
        float a = 0.f;
        for (int xx = 0; xx < 48; xx++) { a += row[xx]; row[xx] = a; }
    }
    __syncthreads();
    // column cumsums
    for (int sid = tid; sid < 9*48; sid += 256) {
        int ch = sid/48, xx = sid - (sid/48)*48;
        float* col = s + ch*2304 + xx;
        float a = 0.f;
        for (int y = 0; y < 48; y++) { a += col[y*48]; col[y*48] = a; }
    }
    __syncthreads();
    float vc[8];
    #pragma unroll
    for (int j = 0; j < 8; j++) vc[j] = g_vc[h*8+j];
    for (int p = tid; p < 2304; p += 256) {
        int y = p/48, xx = p - y*48;
        int iC  = p;
        int iRT = y*48 + 47;
        int iCB = 47*48 + xx;
        int iT  = 2303;
        int iCm = y*48 + xx - 1;
        int iUp = (y-1)*48 + xx;
        int iUR = (y-1)*48 + 47;
        int iCL = 47*48 + xx - 1;
        int iUL = (y-1)*48 + xx - 1;
        bool hx = xx > 0, hy = y > 0;
        float rd[4];
        {
            const float* C = s;
            float tl = C[iC];
            float tr = C[iRT] - (hx ? C[iCm] : 0.f);
            float bl = C[iCB] - (hy ? C[iUp] : 0.f);
            float br = C[iT] - (hy ? C[iUR] : 0.f) - (hx ? C[iCL] : 0.f) + ((hx&&hy) ? C[iUL] : 0.f);
            rd[0] = 1.f/(ecls+tl); rd[1] = 1.f/(ecls+tr);
            rd[2] = 1.f/(ecls+bl); rd[3] = 1.f/(ecls+br);
        }
        float out[4][8];
        #pragma unroll
        for (int j = 0; j < 8; j++) {
            const float* C = s + (1+j)*2304;
            float tl = C[iC];
            float tr = C[iRT] - (hx ? C[iCm] : 0.f);
            float bl = C[iCB] - (hy ? C[iUp] : 0.f);
            float br = C[iT] - (hy ? C[iUR] : 0.f) - (hx ? C[iCL] : 0.f) + ((hx&&hy) ? C[iUL] : 0.f);
            float base = ecls*vc[j];
            out[0][j] = (base+tl)*rd[0];
            out[1][j] = (base+tr)*rd[1];
            out[2][j] = (base+bl)*rd[2];
            out[3][j] = (base+br)*rd[3];
        }
        float* op = g_cls + ((size_t)(b*NTOK + p)*4)*64 + h*8;
        #pragma unroll
        for (int r = 0; r < 4; r++) {
            float4 v0 = make_float4(out[r][0], out[r][1], out[r][2], out[r][3]);
            float4 v1 = make_float4(out[r][4], out[r][5], out[r][6], out[r][7]);
            *(float4*)(op + r*64)     = v0;
            *(float4*)(op + r*64 + 4) = v1;
        }
    }
}

// ---------------- K4: fused epilogue ----------------
__global__ void __launch_bounds__(512) k_epi(const float* __restrict__ Wwproj,
                                             const float* __restrict__ bwproj,
                                             float* __restrict__ outp)
{
    extern __shared__ float s[];
    float* sreg = s;                 // [64 tok][4 r][64 e]  = 16384
    float* sxn  = s + 16384;         // [64 d][68]           = 4352
    float* smix = s + 16384 + 4352;  // [64 g][68]           = 4352
    float* wbuf = s + 16384 + 8704;  // [64][65]             = 4160
    int tid = threadIdx.x, warp = tid>>5, lane = tid&31;
    int tok0 = blockIdx.x*64;
    int tb = warp*4;

    for (int i = tid; i < 4096; i += 512) {
        int t = i>>6, d = i&63;
        sxn[d*68 + t] = g_xn[(size_t)(tok0+t)*64 + d];
    }
    for (int i = tid; i < 16384; i += 512)
        sreg[i] = g_cls[(size_t)tok0*256 + i];
    for (int i = tid; i < 4096; i += 512)
        wbuf[(i&63)*65 + (i>>6)] = Wwproj[i];               // wbuf[d][e] = Wwproj[e][d]
    __syncthreads();

    // regions = cls @ Wwproj^T + bwproj (in-place in sreg, each warp its 4 tokens)
    {
        float acc[4][4][2];
        float b0 = bwproj[lane], b1 = bwproj[lane+32];
        #pragma unroll
        for (int t = 0; t < 4; t++)
            #pragma unroll
            for (int r = 0; r < 4; r++) { acc[t][r][0] = b0; acc[t][r][1] = b1; }
        for (int d = 0; d < 64; d++) {
            float w0 = wbuf[d*65+lane], w1 = wbuf[d*65+lane+32];
            #pragma unroll
            for (int t = 0; t < 4; t++) {
                const float* cp = sreg + (tb+t)*256 + d;
                #pragma unroll
                for (int r = 0; r < 4; r++) {
                    float c = cp[r*64];
                    acc[t][r][0] += c*w0;
                    acc[t][r][1] += c*w1;
                }
            }
        }
        __syncwarp();
        #pragma unroll
        for (int t = 0; t < 4; t++)
            #pragma unroll
            for (int r = 0; r < 4; r++) {
                sreg[(tb+t)*256 + r*64 + lane]      = acc[t][r][0];
                sreg[(tb+t)*256 + r*64 + lane + 32] = acc[t][r][1];
            }
    }
    __syncthreads();

    float out[4][2] = {{0.f,0.f},{0.f,0.f},{0.f,0.f},{0.f,0.f}};
    for (int h = 0; h < 8; h++) {
        for (int i = tid; i < 4096; i += 512)
            wbuf[(i>>6)*65 + (i&63)] = g_P[h*4096 + i];     // wbuf[d][e] = P[d][e]
        __syncthreads();
        float u0 = g_u[h*64+lane], u1 = g_u[h*64+lane+32];
        float q0[4], q1[4];
        #pragma unroll
        for (int t = 0; t < 4; t++) { q0[t] = u0; q1[t] = u1; }
        for (int d = 0; d < 64; d++) {
            float p0 = wbuf[d*65+lane], p1 = wbuf[d*65+lane+32];
            float4 xv = *(const float4*)(sxn + d*68 + tb);
            q0[0] += xv.x*p0; q1[0] += xv.x*p1;
            q0[1] += xv.y*p0; q1[1] += xv.y*p1;
            q0[2] += xv.z*p0; q1[2] += xv.z*p1;
            q0[3] += xv.w*p0; q1[3] += xv.w*p1;
        }
        #pragma unroll
        for (int t = 0; t < 4; t++) {
            const float* rg = sreg + (tb+t)*256;
            float sc[4];
            #pragma unroll
            for (int r = 0; r < 4; r++)
                sc[r] = q0[t]*rg[r*64+lane] + q1[t]*rg[r*64+lane+32];
            #pragma unroll
            for (int off = 16; off; off >>= 1) {
                #pragma unroll
                for (int r = 0; r < 4; r++)
                    sc[r] += __shfl_xor_sync(0xffffffffu, sc[r], off);
            }
            float mx = fmaxf(fmaxf(sc[0],sc[1]), fmaxf(sc[2],sc[3]));
            float e0 = __expf(sc[0]-mx), e1 = __expf(sc[1]-mx);
            float e2 = __expf(sc[2]-mx), e3 = __expf(sc[3]-mx);
            float inv = 1.f/(e0+e1+e2+e3);
            float a0 = e0*inv, a1 = e1*inv, a2 = e2*inv, a3 = e3*inv;
            float m0 = a0*rg[lane]    + a1*rg[64+lane]    + a2*rg[128+lane]    + a3*rg[192+lane];
            float m1 = a0*rg[lane+32] + a1*rg[64+lane+32] + a2*rg[128+lane+32] + a3*rg[192+lane+32];
            smix[lane*68 + tb + t]      = m0;
            smix[(lane+32)*68 + tb + t] = m1;
        }
        __syncthreads();
        for (int i = tid; i < 4096; i += 512)
            wbuf[(i>>6)*65 + (i&63)] = g_Q[h*4096 + i];     // wbuf[g][o] = Q[g][o]
        __syncthreads();
        for (int g = 0; g < 64; g++) {
            float w0 = wbuf[g*65+lane], w1 = wbuf[g*65+lane+32];
            float4 mv = *(const float4*)(smix + g*68 + tb);
            out[0][0] += mv.x*w0; out[0][1] += mv.x*w1;
            out[1][0] += mv.y*w0; out[1][1] += mv.y*w1;
            out[2][0] += mv.z*w0; out[2][1] += mv.z*w1;
            out[3][0] += mv.w*w0; out[3][1] += mv.w*w1;
        }
        __syncthreads();
    }
    float c0 = g_cvec[lane], c1 = g_cvec[lane+32];
    #pragma unroll
    for (int t = 0; t < 4; t++) {
        outp[(size_t)(tok0+tb+t)*64 + lane]      = out[t][0] + c0;
        outp[(size_t)(tok0+tb+t)*64 + lane + 32] = out[t][1] + c1;
    }
}

// ---------------- launch ----------------
extern "C" void kernel_launch(void* const* d_in, const int* in_sizes, int n_in,
                              void* d_out, int out_size)
{
    const float* x      = (const float*)d_in[0];
    const float* ln_g   = (const float*)d_in[1];
    const float* ln_b   = (const float*)d_in[2];
    const float* Wqkv   = (const float*)d_in[3];
    const float* bqkv   = (const float*)d_in[4];
    const float* cls_t  = (const float*)d_in[5];
    const float* Wwqkv  = (const float*)d_in[6];
    const float* bwqkv  = (const float*)d_in[7];
    const float* Wwproj = (const float*)d_in[8];
    const float* bwproj = (const float*)d_in[9];
    const float* Wraq   = (const float*)d_in[10];
    const float* Wrak   = (const float*)d_in[11];
    const float* Wrav   = (const float*)d_in[12];
    const float* Wrao   = (const float*)d_in[13];
    const float* brao   = (const float*)d_in[14];
    const float* Wout   = (const float*)d_in[15];
    const float* bout   = (const float*)d_in[16];
    float* outp = (float*)d_out;

    cudaFuncSetAttribute(k_quad, cudaFuncAttributeMaxDynamicSharedMemorySize, 9*2304*4);
    cudaFuncSetAttribute(k_epi,  cudaFuncAttributeMaxDynamicSharedMemorySize, 29248*4);

    precompA<<<1, 256>>>(bqkv, cls_t, Wwqkv, bwqkv, Wraq, Wrak, Wrao, Wrav, brao, Wout, bout);
    precompB<<<16, 256>>>(Wqkv, Wout);
    k_ln<<<TOKENS/8, 256>>>(x, ln_g, ln_b, Wwqkv, bwqkv);
    k_max<<<BB*NHEADS, 256>>>();
    k_quad<<<BB*NHEADS, 256, 9*2304*4>>>();
    k_epi<<<TOKENS/64, 512, 29248*4>>>(Wwproj, bwproj, outp);
}

// round 3
// speedup vs baseline: 1.4834x; 1.4834x over previous
#include <cuda_runtime.h>
#include <math.h>

#define BB 64
#define NTOK 2304
#define DD 64
#define NHEADS 8
#define TOKENS (BB*NTOK)   // 147456

// ---------------- scratch (device globals; no allocations) ----------------
__device__ float g_xn[TOKENS*DD];
__device__ float g_v[TOKENS*DD];                 // head-major: [(b*8+h)*2304 + p]*8 + j
__device__ float g_logits[BB*NHEADS*NTOK];
__device__ float g_m[BB*NHEADS];
__device__ float g_cls[(size_t)TOKENS*4*DD];     // [tok][r][64e]
__device__ float g_WL[NHEADS*DD];
__device__ float g_bL[NHEADS];
__device__ float g_vc[DD];
__device__ float g_clslogit[NHEADS];
__device__ float g_G[DD*DD];
__device__ float g_R[DD*DD];
__device__ float g_u[NHEADS*DD];
__device__ float g_cvec[DD];
__device__ float g_P[NHEADS*DD*DD];
__device__ float g_Q[NHEADS*DD*DD];
__device__ float2 g_P2p[NHEADS*2048];            // [h][f][lane] = (P2[f,l], P2[f,l+32])
__device__ float2 g_Q2p[NHEADS*2048];            // [h][e][lane] = (Q2[e,l], Q2[e,l+32])
__device__ float g_u2[NHEADS*DD];
__device__ float g_cvec2[DD];

__device__ __forceinline__ float kscale() { return 0.35355339059327373f; } // 8^-0.5

// ---------------- f32x2 helpers ----------------
typedef unsigned long long ull;
__device__ __forceinline__ ull pack2(float x, float y) {
    ull r; asm("mov.b64 %0, {%1,%2};" : "=l"(r) : "f"(x), "f"(y)); return r;
}
__device__ __forceinline__ void unpack2(ull v, float& x, float& y) {
    asm("mov.b64 {%0,%1}, %2;" : "=f"(x), "=f"(y) : "l"(v));
}
__device__ __forceinline__ void ffma2(ull& acc, ull a, ull b) {
    asm("fma.rn.f32x2 %0, %1, %2, %0;" : "+l"(acc) : "l"(a), "l"(b));
}

// ---------------- precompute A ----------------
__global__ void precompA(const float* __restrict__ bqkv,
                         const float* __restrict__ cls_tok,
                         const float* __restrict__ Wwqkv, const float* __restrict__ bwqkv,
                         const float* __restrict__ Wraq, const float* __restrict__ Wrak,
                         const float* __restrict__ Wrao, const float* __restrict__ Wrav,
                         const float* __restrict__ brao,
                         const float* __restrict__ Wout, const float* __restrict__ bout)
{
    __shared__ float scq[192];
    __shared__ float sqc[64];
    int tid = threadIdx.x;
    if (tid < 192) {
        float a = bwqkv[tid];
        for (int d = 0; d < 64; d++) a += Wwqkv[tid*64+d]*cls_tok[d];
        scq[tid] = a;
    }
    __syncthreads();
    if (tid < 64) { sqc[tid] = scq[tid]*kscale(); g_vc[tid] = scq[128+tid]; }
    __syncthreads();
    if (tid < 8) {
        float cl = 0.f, bl = 0.f;
        for (int j = 0; j < 8; j++) {
            cl += sqc[tid*8+j]*scq[64+tid*8+j];
            bl += sqc[tid*8+j]*bwqkv[64+tid*8+j];
        }
        g_clslogit[tid] = cl; g_bL[tid] = bl;
    }
    for (int i = tid; i < 512; i += 256) {
        int h = i>>6, d = i&63;
        float a = 0.f;
        for (int j = 0; j < 8; j++) a += sqc[h*8+j]*Wwqkv[(64+h*8+j)*64+d];
        g_WL[i] = a;
    }
    for (int i = tid; i < 4096; i += 256) {
        int dd = i>>6, g = i&63;
        float a = 0.f;
        for (int e = 0; e < 64; e++) a += Wraq[e*64+dd]*Wrak[e*64+g];
        g_G[i] = a;
    }
    for (int i = tid; i < 4096; i += 256) {
        int a_ = i>>6, g = i&63;
        float sR = 0.f;
        for (int c = 0; c < 64; c++) sR += Wrao[a_*64+c]*Wrav[c*64+g];
        g_R[i] = sR;
    }
    __syncthreads();
    for (int i = tid; i < 512; i += 256) {
        int h = i>>6, g = i&63;
        float su = 0.f;
        for (int dd = 0; dd < 64; dd++) su += bqkv[h*64+dd]*g_G[dd*64+g];
        g_u[i] = su*kscale();
    }
    if (tid < 64) {
        float sc = bout[tid];
        for (int k = 0; k < 512; k++) sc += Wout[tid*512+k]*brao[k&63];
        g_cvec[tid] = sc;
    }
}

// ---------------- precompute B: P_h and Q_h ----------------
__global__ void precompB(const float* __restrict__ Wqkv, const float* __restrict__ Wout)
{
    __shared__ float sM[4096];
    int h = blockIdx.x & 7;
    int which = blockIdx.x >> 3;
    int tid = threadIdx.x;
    const float* src = which ? g_R : g_G;
    for (int i = tid; i < 4096; i += 256) sM[i] = src[i];
    __syncthreads();
    if (which == 0) {
        for (int i = tid; i < 4096; i += 256) {
            int f = i>>6, g = i&63;
            float s = 0.f;
            for (int dd = 0; dd < 64; dd++) s += Wqkv[(h*64+dd)*64 + f]*sM[dd*64+g];
            g_P[h*4096 + i] = s*kscale();
        }
    } else {
        for (int i = tid; i < 4096; i += 256) {
            int g = i>>6, o = i&63;
            float s = 0.f;
            for (int a = 0; a < 64; a++) s += Wout[o*512 + h*64 + a]*sM[a*64+g];
            g_Q[h*4096 + i] = s;
        }
    }
}

// ---------------- precompute C: P2/Q2 pair layouts, u2 ----------------
__global__ void precompC(const float* __restrict__ Wwproj)
{
    __shared__ float sW[4096];   // [g][e] = Wwproj[g*64+e]
    __shared__ float sM[4096];
    int h = blockIdx.x & 7, which = blockIdx.x >> 3, tid = threadIdx.x;
    for (int i = tid; i < 4096; i += 256) sW[i] = Wwproj[i];
    if (which == 0) for (int i = tid; i < 4096; i += 256) sM[i] = g_P[h*4096+i]; // [f][g]
    else            for (int i = tid; i < 4096; i += 256) sM[i] = g_Q[h*4096+i]; // [g][o]
    __syncthreads();
    if (which == 0) {
        for (int i = tid; i < 2048; i += 256) {
            int f = i>>5, l = i&31;
            float a = 0.f, bv = 0.f;
            for (int g = 0; g < 64; g++) {
                float p = sM[f*64+g];
                a  += p*sW[g*64+l];
                bv += p*sW[g*64+l+32];
            }
            g_P2p[h*2048+i] = make_float2(a, bv);
        }
        if (tid < 64) {
            float a = 0.f;
            for (int g = 0; g < 64; g++) a += g_u[h*64+g]*sW[g*64+tid];
            g_u2[h*64+tid] = a;
        }
    } else {
        for (int i = tid; i < 2048; i += 256) {
            int e = i>>5, l = i&31;
            float a = 0.f, bv = 0.f;
            for (int g = 0; g < 64; g++) {
                float we = sW[g*64+e];
                a  += we*sM[g*64+l];
                bv += we*sM[g*64+l+32];
            }
            g_Q2p[h*2048+i] = make_float2(a, bv);
        }
    }
}

// ---------------- precompute D: cvec2 ----------------
__global__ void precompD(const float* __restrict__ bwproj)
{
    int o = threadIdx.x;
    if (o < 64) {
        float a = g_cvec[o];
        for (int h = 0; h < 8; h++)
            for (int g = 0; g < 64; g++) a += bwproj[g]*g_Q[h*4096 + g*64 + o];
        g_cvec2[o] = a;
    }
}

// ---------------- K1: LayerNorm + logits + v projection (warp per token) ----------------
__global__ void __launch_bounds__(256) k_ln(const float* __restrict__ x,
     const float* __restrict__ ln_g, const float* __restrict__ ln_b,
     const float* __restrict__ Wwqkv, const float* __restrict__ bwqkv)
{
    __shared__ float swv[64*65];
    __shared__ float sWL[8*65];
    __shared__ float sxb[8*64];
    __shared__ float sbias[64];
    int tid = threadIdx.x, warp = tid>>5, lane = tid&31;
    for (int i = tid; i < 4096; i += 256)
        swv[(i&63)*65 + (i>>6)] = Wwqkv[8192 + i];          // swv[d][e] = Wwv[e][d]
    for (int i = tid; i < 512; i += 256)
        sWL[(i>>6)*65 + (i&63)] = g_WL[i];
    if (tid < 64) sbias[tid] = bwqkv[128+tid];
    __syncthreads();
    int token = blockIdx.x*8 + warp;
    float x0 = x[token*64 + lane];
    float x1 = x[token*64 + lane + 32];
    float s = x0 + x1, ss = x0*x0 + x1*x1;
    #pragma unroll
    for (int off = 16; off; off >>= 1) {
        s  += __shfl_xor_sync(0xffffffffu, s,  off);
        ss += __shfl_xor_sync(0xffffffffu, ss, off);
    }
    float mu = s*(1.f/64.f);
    float var = ss*(1.f/64.f) - mu*mu;
    float rstd = rsqrtf(var + 1e-5f);
    float xn0 = (x0-mu)*rstd*ln_g[lane] + ln_b[lane];
    float xn1 = (x1-mu)*rstd*ln_g[lane+32] + ln_b[lane+32];
    g_xn[token*64+lane] = xn0;
    g_xn[token*64+lane+32] = xn1;
    sxb[warp*64+lane] = xn0; sxb[warp*64+lane+32] = xn1;
    __syncwarp();
    float v0 = sbias[lane], v1 = sbias[lane+32];
    #pragma unroll 8
    for (int d = 0; d < 64; d++) {
        float xd = sxb[warp*64+d];
        v0 += xd*swv[d*65+lane];
        v1 += xd*swv[d*65+lane+32];
    }
    int b = token/NTOK, nn = token - b*NTOK;
    // head-major v layout
    {
        int h0 = lane>>3, j0 = lane&7;
        g_v[((size_t)(b*8+h0)*NTOK + nn)*8 + j0] = v0;
        int h1 = (lane+32)>>3;
        g_v[((size_t)(b*8+h1)*NTOK + nn)*8 + j0] = v1;
    }
    if (lane < 8) {
        float a = g_bL[lane];
        #pragma unroll 8
        for (int d = 0; d < 64; d++) a += sxb[warp*64+d]*sWL[lane*65+d];
        g_logits[(b*8+lane)*NTOK + nn] = a;
    }
}

// ---------------- K2: per-(b,h) max ----------------
__global__ void k_max()
{
    __shared__ float red[256];
    int bid = blockIdx.x, tid = threadIdx.x;
    float m = -1e30f;
    for (int i = tid; i < NTOK; i += 256) m = fmaxf(m, g_logits[bid*NTOK + i]);
    red[tid] = m;
    __syncthreads();
    for (int s = 128; s; s >>= 1) {
        if (tid < s) red[tid] = fmaxf(red[tid], red[tid+s]);
        __syncthreads();
    }
    if (tid == 0) g_m[bid] = fmaxf(red[0], g_clslogit[bid&7]);
}

// ---------------- K3: exp + integral-image quad sums + cls_out ----------------
__global__ void __launch_bounds__(256) k_quad()
{
    extern __shared__ float s[];  // 9 * 2304 floats
    int bid = blockIdx.x, tid = threadIdx.x;
    int b = bid>>3, h = bid&7;
    float m = g_m[bid];
    float ecls = __expf(g_clslogit[h] - m);
    for (int p = tid; p < 2304; p += 256)
        s[p] = __expf(g_logits[bid*NTOK + p] - m);
    __syncthreads();
    const float* vbase = g_v + (size_t)bid*NTOK*8;
    for (int i = tid; i < 2304*8; i += 256) {
        int p = i>>3, j = i&7;
        s[(1+j)*2304 + p] = s[p] * vbase[i];
    }
    __syncthreads();
    // row cumsums (9 channels x 48 rows)
    for (int sid = tid; sid < 9*48; sid += 256) {
        int ch = sid/48, y = sid - (sid/48)*48;
        float* row = s + ch*2304 + y*48;
        float a = 0.f;
        for (int xx = 0; xx < 48; xx++) { a += row[xx]; row[xx] = a; }
    }
    __syncthreads();
    // column cumsums
    for (int sid = tid; sid < 9*48; sid += 256) {
        int ch = sid/48, xx = sid - (sid/48)*48;
        float* col = s + ch*2304 + xx;
        float a = 0.f;
        for (int y = 0; y < 48; y++) { a += col[y*48]; col[y*48] = a; }
    }
    __syncthreads();
    float vc[8];
    #pragma unroll
    for (int j = 0; j < 8; j++) vc[j] = g_vc[h*8+j];
    for (int p = tid; p < 2304; p += 256) {
        int y = p/48, xx = p - y*48;
        int iC  = p;
        int iRT = y*48 + 47;
        int iCB = 47*48 + xx;
        int iT  = 2303;
        int iCm = y*48 + xx - 1;
        int iUp = (y-1)*48 + xx;
        int iUR = (y-1)*48 + 47;
        int iCL = 47*48 + xx - 1;
        int iUL = (y-1)*48 + xx - 1;
        bool hx = xx > 0, hy = y > 0;
        float rd[4];
        {
            const float* C = s;
            float tl = C[iC];
            float tr = C[iRT] - (hx ? C[iCm] : 0.f);
            float bl = C[iCB] - (hy ? C[iUp] : 0.f);
            float br = C[iT] - (hy ? C[iUR] : 0.f) - (hx ? C[iCL] : 0.f) + ((hx&&hy) ? C[iUL] : 0.f);
            rd[0] = 1.f/(ecls+tl); rd[1] = 1.f/(ecls+tr);
            rd[2] = 1.f/(ecls+bl); rd[3] = 1.f/(ecls+br);
        }
        float out[4][8];
        #pragma unroll
        for (int j = 0; j < 8; j++) {
            const float* C = s + (1+j)*2304;
            float tl = C[iC];
            float tr = C[iRT] - (hx ? C[iCm] : 0.f);
            float bl = C[iCB] - (hy ? C[iUp] : 0.f);
            float br = C[iT] - (hy ? C[iUR] : 0.f) - (hx ? C[iCL] : 0.f) + ((hx&&hy) ? C[iUL] : 0.f);
            float base = ecls*vc[j];
            out[0][j] = (base+tl)*rd[0];
            out[1][j] = (base+tr)*rd[1];
            out[2][j] = (base+bl)*rd[2];
            out[3][j] = (base+br)*rd[3];
        }
        float* op = g_cls + ((size_t)(b*NTOK + p)*4)*64 + h*8;
        #pragma unroll
        for (int r = 0; r < 4; r++) {
            float4 v0 = make_float4(out[r][0], out[r][1], out[r][2], out[r][3]);
            float4 v1 = make_float4(out[r][4], out[r][5], out[r][6], out[r][7]);
            *(float4*)(op + r*64)     = v0;
            *(float4*)(op + r*64 + 4) = v1;
        }
    }
}

// ---------------- K4: fused epilogue (f32x2, regions eliminated) ----------------
// 256 threads = 8 warps; 8 tokens/warp; 64 tokens/block.
#define XS 68
__global__ void __launch_bounds__(256) k_epi(float* __restrict__ outp)
{
    extern __shared__ float s[];
    float*  sxn   = s;               // [64 f][XS]   (token-major rows)
    float*  scmix = s + 64*XS;       // [64 e][XS]
    float2* wsP   = (float2*)(s + 2*64*XS);          // [64 f][32]
    float2* wsQ   = wsP + 2048;                      // [64 e][32]
    int tid = threadIdx.x, warp = tid>>5, lane = tid&31;
    int tok0 = blockIdx.x*64;
    int tb = warp*8;

    for (int i = tid; i < 4096; i += 256) {
        int t = i>>6, d = i&63;
        sxn[d*XS + t] = g_xn[(size_t)(tok0+t)*64 + d];
    }

    ull accO[2][4];
    #pragma unroll
    for (int e = 0; e < 2; e++)
        #pragma unroll
        for (int pr = 0; pr < 4; pr++) accO[e][pr] = pack2(0.f, 0.f);

    for (int h = 0; h < 8; h++) {
        __syncthreads();   // protect ws (and first-iter sxn) before overwrite/use
        for (int i = tid; i < 2048; i += 256) {
            wsP[i] = g_P2p[h*2048 + i];
            wsQ[i] = g_Q2p[h*2048 + i];
        }
        __syncthreads();

        // qp2[e] = sum_f xn[f]*P2[f,e] + u2[e], e = lane / lane+32, 8 tokens packed in pairs
        float u2a = g_u2[h*64 + lane];
        float u2b = g_u2[h*64 + lane + 32];
        ull aQ[2][4];
        #pragma unroll
        for (int pr = 0; pr < 4; pr++) { aQ[0][pr] = pack2(u2a,u2a); aQ[1][pr] = pack2(u2b,u2b); }
        #pragma unroll 8
        for (int f = 0; f < 64; f++) {
            float2 w = wsP[f*32 + lane];
            ull p0 = pack2(w.x, w.x);
            ull p1 = pack2(w.y, w.y);
            const ulonglong2* xr = (const ulonglong2*)(sxn + f*XS + tb);
            ulonglong2 xa = xr[0];
            ulonglong2 xb = xr[1];
            ffma2(aQ[0][0], xa.x, p0); ffma2(aQ[0][1], xa.y, p0);
            ffma2(aQ[0][2], xb.x, p0); ffma2(aQ[0][3], xb.y, p0);
            ffma2(aQ[1][0], xa.x, p1); ffma2(aQ[1][1], xa.y, p1);
            ffma2(aQ[1][2], xb.x, p1); ffma2(aQ[1][3], xb.y, p1);
        }
        float q0[8], q1[8];
        #pragma unroll
        for (int pr = 0; pr < 4; pr++) {
            unpack2(aQ[0][pr], q0[2*pr], q0[2*pr+1]);
            unpack2(aQ[1][pr], q1[2*pr], q1[2*pr+1]);
        }

        // scores + softmax + cmix, per token
        #pragma unroll
        for (int t = 0; t < 8; t++) {
            const float* cp = g_cls + (size_t)(tok0 + tb + t)*256 + lane;
            float c0r0 = cp[0],   c1r0 = cp[32];
            float c0r1 = cp[64],  c1r1 = cp[96];
            float c0r2 = cp[128], c1r2 = cp[160];
            float c0r3 = cp[192], c1r3 = cp[224];
            float sc0 = q0[t]*c0r0 + q1[t]*c1r0;
            float sc1 = q0[t]*c0r1 + q1[t]*c1r1;
            float sc2 = q0[t]*c0r2 + q1[t]*c1r2;
            float sc3 = q0[t]*c0r3 + q1[t]*c1r3;
            #pragma unroll
            for (int off = 16; off; off >>= 1) {
                sc0 += __shfl_xor_sync(0xffffffffu, sc0, off);
                sc1 += __shfl_xor_sync(0xffffffffu, sc1, off);
                sc2 += __shfl_xor_sync(0xffffffffu, sc2, off);
                sc3 += __shfl_xor_sync(0xffffffffu, sc3, off);
            }
            float mx = fmaxf(fmaxf(sc0,sc1), fmaxf(sc2,sc3));
            float e0 = __expf(sc0-mx), e1 = __expf(sc1-mx);
            float e2 = __expf(sc2-mx), e3 = __expf(sc3-mx);
            float inv = 1.f/(e0+e1+e2+e3);
            float a0 = e0*inv, a1 = e1*inv, a2 = e2*inv, a3 = e3*inv;
            scmix[lane*XS + tb + t]      = a0*c0r0 + a1*c0r1 + a2*c0r2 + a3*c0r3;
            scmix[(lane+32)*XS + tb + t] = a0*c1r0 + a1*c1r1 + a2*c1r2 + a3*c1r3;
        }
        __syncwarp();

        // out[o] += sum_e cmix[e]*Q2[e,o]
        #pragma unroll 8
        for (int e = 0; e < 64; e++) {
            float2 w = wsQ[e*32 + lane];
            ull p0 = pack2(w.x, w.x);
            ull p1 = pack2(w.y, w.y);
            const ulonglong2* mr = (const ulonglong2*)(scmix + e*XS + tb);
            ulonglong2 ma = mr[0];
            ulonglong2 mb = mr[1];
            ffma2(accO[0][0], ma.x, p0); ffma2(accO[0][1], ma.y, p0);
            ffma2(accO[0][2], mb.x, p0); ffma2(accO[0][3], mb.y, p0);
            ffma2(accO[1][0], ma.x, p1); ffma2(accO[1][1], ma.y, p1);
            ffma2(accO[1][2], mb.x, p1); ffma2(accO[1][3], mb.y, p1);
        }
    }

    float o0[8], o1[8];
    #pragma unroll
    for (int pr = 0; pr < 4; pr++) {
        unpack2(accO[0][pr], o0[2*pr], o0[2*pr+1]);
        unpack2(accO[1][pr], o1[2*pr], o1[2*pr+1]);
    }
    float c0 = g_cvec2[lane], c1 = g_cvec2[lane+32];
    #pragma unroll
    for (int t = 0; t < 8; t++) {
        outp[(size_t)(tok0+tb+t)*64 + lane]      = o0[t] + c0;
        outp[(size_t)(tok0+tb+t)*64 + lane + 32] = o1[t] + c1;
    }
}

// ---------------- launch ----------------
extern "C" void kernel_launch(void* const* d_in, const int* in_sizes, int n_in,
                              void* d_out, int out_size)
{
    const float* x      = (const float*)d_in[0];
    const float* ln_g   = (const float*)d_in[1];
    const float* ln_b   = (const float*)d_in[2];
    const float* Wqkv   = (const float*)d_in[3];
    const float* bqkv   = (const float*)d_in[4];
    const float* cls_t  = (const float*)d_in[5];
    const float* Wwqkv  = (const float*)d_in[6];
    const float* bwqkv  = (const float*)d_in[7];
    const float* Wwproj = (const float*)d_in[8];
    const float* bwproj = (const float*)d_in[9];
    const float* Wraq   = (const float*)d_in[10];
    const float* Wrak   = (const float*)d_in[11];
    const float* Wrav   = (const float*)d_in[12];
    const float* Wrao   = (const float*)d_in[13];
    const float* brao   = (const float*)d_in[14];
    const float* Wout   = (const float*)d_in[15];
    const float* bout   = (const float*)d_in[16];
    float* outp = (float*)d_out;

    int epi_smem = (2*64*XS)*4 + 2*2048*8;   // 34816 + 32768 = 67584 B
    cudaFuncSetAttribute(k_quad, cudaFuncAttributeMaxDynamicSharedMemorySize, 9*2304*4);
    cudaFuncSetAttribute(k_epi,  cudaFuncAttributeMaxDynamicSharedMemorySize, epi_smem);

    precompA<<<1, 256>>>(bqkv, cls_t, Wwqkv, bwqkv, Wraq, Wrak, Wrao, Wrav, brao, Wout, bout);
    precompB<<<16, 256>>>(Wqkv, Wout);
    precompC<<<16, 256>>>(Wwproj);
    precompD<<<1, 64>>>(bwproj);
    k_ln<<<TOKENS/8, 256>>>(x, ln_g, ln_b, Wwqkv, bwqkv);
    k_max<<<BB*NHEADS, 256>>>();
    k_quad<<<BB*NHEADS, 256, 9*2304*4>>>();
    k_epi<<<TOKENS/64, 256, epi_smem>>>(outp);
}

// round 4
// speedup vs baseline: 1.7026x; 1.1478x over previous
#include <cuda_runtime.h>
#include <math.h>

#define BB 64
#define NTOK 2304
#define DD 64
#define NHEADS 8
#define TOKENS (BB*NTOK)   // 147456

// ---------------- scratch (device globals; no allocations) ----------------
__device__ float g_xn[TOKENS*DD];
__device__ float g_v[TOKENS*DD];                 // head-major: [(b*8+h)*2304 + p]*8 + j
__device__ float g_logits[BB*NHEADS*NTOK];
__device__ float g_m[BB*NHEADS];
__device__ float g_cls[(size_t)TOKENS*4*DD];     // [tok][r][64e]
__device__ float g_WL[NHEADS*DD];
__device__ float g_bL[NHEADS];
__device__ float g_vc[DD];
__device__ float g_clslogit[NHEADS];
__device__ float g_G[DD*DD];
__device__ float g_R[DD*DD];
__device__ float g_u[NHEADS*DD];
__device__ float g_cvec[DD];
__device__ float g_P[NHEADS*DD*DD];
__device__ float g_Q[NHEADS*DD*DD];
__device__ float4 g_P4p[NHEADS*1024];   // [h][f2][lane] = (P2[2f2][l],P2[2f2][l+32],P2[2f2+1][l],P2[2f2+1][l+32])
__device__ float4 g_Q4p[NHEADS*1024];   // [h][e2][lane] = (Q2[2e2][l],Q2[2e2][l+32],Q2[2e2+1][l],Q2[2e2+1][l+32])
__device__ float g_u2[NHEADS*DD];
__device__ float g_cvec2[DD];

__device__ __forceinline__ float kscale() { return 0.35355339059327373f; } // 8^-0.5

// ---------------- f32x2 helpers ----------------
typedef unsigned long long ull;
__device__ __forceinline__ ull pack2(float x, float y) {
    ull r; asm("mov.b64 %0, {%1,%2};" : "=l"(r) : "f"(x), "f"(y)); return r;
}
__device__ __forceinline__ void unpack2(ull v, float& x, float& y) {
    asm("mov.b64 {%0,%1}, %2;" : "=f"(x), "=f"(y) : "l"(v));
}
__device__ __forceinline__ void ffma2(ull& acc, ull a, ull b) {
    asm("fma.rn.f32x2 %0, %1, %2, %0;" : "+l"(acc) : "l"(a), "l"(b));
}

// ---------------- precompute A (small, 1 block) ----------------
__global__ void precompA(const float* __restrict__ cls_tok,
                         const float* __restrict__ Wwqkv, const float* __restrict__ bwqkv,
                         const float* __restrict__ brao,
                         const float* __restrict__ Wout, const float* __restrict__ bout)
{
    __shared__ float scq[192];
    __shared__ float sqc[64];
    __shared__ float sred[256];
    int tid = threadIdx.x;
    if (tid < 192) {
        float a = bwqkv[tid];
        for (int d = 0; d < 64; d++) a += Wwqkv[tid*64+d]*cls_tok[d];
        scq[tid] = a;
    }
    __syncthreads();
    if (tid < 64) { sqc[tid] = scq[tid]*kscale(); g_vc[tid] = scq[128+tid]; }
    __syncthreads();
    if (tid < 8) {
        float cl = 0.f, bl = 0.f;
        for (int j = 0; j < 8; j++) {
            cl += sqc[tid*8+j]*scq[64+tid*8+j];
            bl += sqc[tid*8+j]*bwqkv[64+tid*8+j];
        }
        g_clslogit[tid] = cl; g_bL[tid] = bl;
    }
    for (int i = tid; i < 512; i += 256) {
        int h = i>>6, d = i&63;
        float a = 0.f;
        for (int j = 0; j < 8; j++) a += sqc[h*8+j]*Wwqkv[(64+h*8+j)*64+d];
        g_WL[i] = a;
    }
    // cvec: 4 threads per output
    {
        int o = tid>>2, q = tid&3;
        float a = (q==0) ? bout[o] : 0.f;
        for (int k = q*128; k < q*128+128; k++) a += Wout[o*512+k]*brao[k&63];
        sred[tid] = a;
    }
    __syncthreads();
    if (tid < 64)
        g_cvec[tid] = sred[4*tid] + sred[4*tid+1] + sred[4*tid+2] + sred[4*tid+3];
}

// ---------------- precompute G/R: grid 32 x 256 ----------------
__global__ void precompGR(const float* __restrict__ Wraq, const float* __restrict__ Wrak,
                          const float* __restrict__ Wrao, const float* __restrict__ Wrav)
{
    int which = blockIdx.x >> 4;
    int i = (blockIdx.x & 15)*256 + threadIdx.x;   // 0..4095
    int r0 = i>>6, c0 = i&63;
    if (which == 0) {
        // G[dd][g] = sum_e Wraq[e][dd]*Wrak[e][g]
        float a = 0.f;
        #pragma unroll 8
        for (int e = 0; e < 64; e++) a += Wraq[e*64+r0]*Wrak[e*64+c0];
        g_G[i] = a;
    } else {
        // R[a][g] = sum_c Wrao[a][c]*Wrav[c][g]
        float a = 0.f;
        #pragma unroll 8
        for (int c = 0; c < 64; c++) a += Wrao[r0*64+c]*Wrav[c*64+c0];
        g_R[i] = a;
    }
}

// ---------------- precompute B: P_h, Q_h, u ----------------
__global__ void precompB(const float* __restrict__ Wqkv, const float* __restrict__ Wout,
                         const float* __restrict__ bqkv)
{
    __shared__ float sM[4096];
    int h = blockIdx.x & 7;
    int which = blockIdx.x >> 3;
    int tid = threadIdx.x;
    const float* src = which ? g_R : g_G;
    for (int i = tid; i < 4096; i += 256) sM[i] = src[i];
    __syncthreads();
    if (which == 0) {
        for (int i = tid; i < 4096; i += 256) {
            int f = i>>6, g = i&63;
            float s = 0.f;
            for (int dd = 0; dd < 64; dd++) s += Wqkv[(h*64+dd)*64 + f]*sM[dd*64+g];
            g_P[h*4096 + i] = s*kscale();
        }
        if (tid < 64) {
            float su = 0.f;
            for (int dd = 0; dd < 64; dd++) su += bqkv[h*64+dd]*sM[dd*64+tid];
            g_u[h*64+tid] = su*kscale();
        }
    } else {
        for (int i = tid; i < 4096; i += 256) {
            int g = i>>6, o = i&63;
            float s = 0.f;
            for (int a = 0; a < 64; a++) s += Wout[o*512 + h*64 + a]*sM[a*64+g];
            g_Q[h*4096 + i] = s;
        }
    }
}

// ---------------- precompute C: P2/Q2 in float4 pair layout, u2 ----------------
__global__ void precompC(const float* __restrict__ Wwproj)
{
    extern __shared__ float sc[];
    float* sW = sc;          // [g][e]
    float* sM = sc + 4096;
    float* sO = sc + 8192;
    int h = blockIdx.x & 7, which = blockIdx.x >> 3, tid = threadIdx.x;
    for (int i = tid; i < 4096; i += 256) sW[i] = Wwproj[i];
    if (which == 0) for (int i = tid; i < 4096; i += 256) sM[i] = g_P[h*4096+i]; // [f][g]
    else            for (int i = tid; i < 4096; i += 256) sM[i] = g_Q[h*4096+i]; // [g][o]
    __syncthreads();
    if (which == 0) {
        for (int i = tid; i < 4096; i += 256) {
            int f = i>>6, e = i&63;
            float a = 0.f;
            for (int g = 0; g < 64; g++) a += sM[f*64+g]*sW[g*64+e];
            sO[i] = a;   // P2[f][e]
        }
        if (tid < 64) {
            float a = 0.f;
            for (int g = 0; g < 64; g++) a += g_u[h*64+g]*sW[g*64+tid];
            g_u2[h*64+tid] = a;
        }
        __syncthreads();
        for (int i = tid; i < 1024; i += 256) {
            int k2 = i>>5, l = i&31;
            g_P4p[h*1024+i] = make_float4(sO[(2*k2)*64+l],   sO[(2*k2)*64+l+32],
                                          sO[(2*k2+1)*64+l], sO[(2*k2+1)*64+l+32]);
        }
    } else {
        for (int i = tid; i < 4096; i += 256) {
            int e = i>>6, o = i&63;
            float a = 0.f;
            for (int g = 0; g < 64; g++) a += sW[g*64+e]*sM[g*64+o];
            sO[i] = a;   // Q2[e][o]
        }
        __syncthreads();
        for (int i = tid; i < 1024; i += 256) {
            int k2 = i>>5, l = i&31;
            g_Q4p[h*1024+i] = make_float4(sO[(2*k2)*64+l],   sO[(2*k2)*64+l+32],
                                          sO[(2*k2+1)*64+l], sO[(2*k2+1)*64+l+32]);
        }
    }
}

// ---------------- precompute D: cvec2 (parallel) ----------------
__global__ void precompD(const float* __restrict__ bwproj)
{
    __shared__ float sp[512];
    int tid = threadIdx.x;
    int h = tid>>6, o = tid&63;
    float a = 0.f;
    for (int g = 0; g < 64; g++) a += bwproj[g]*g_Q[h*4096 + g*64 + o];
    sp[tid] = a;
    __syncthreads();
    if (tid < 64) {
        float s = g_cvec[tid];
        for (int hh = 0; hh < 8; hh++) s += sp[hh*64+tid];
        g_cvec2[tid] = s;
    }
}

// ---------------- K1: LayerNorm + logits + v projection (64 tokens/block) ----------------
__global__ void __launch_bounds__(256) k_ln(const float* __restrict__ x,
     const float* __restrict__ ln_g, const float* __restrict__ ln_b,
     const float* __restrict__ Wwqkv, const float* __restrict__ bwqkv)
{
    __shared__ float swv[64*65];
    __shared__ float sWL[8*65];
    __shared__ float sxb[8*64];
    int tid = threadIdx.x, warp = tid>>5, lane = tid&31;
    for (int i = tid; i < 4096; i += 256)
        swv[(i&63)*65 + (i>>6)] = Wwqkv[8192 + i];          // swv[d][e] = Wwv[e][d]
    for (int i = tid; i < 512; i += 256)
        sWL[(i>>6)*65 + (i&63)] = g_WL[i];
    __syncthreads();
    float ga0 = ln_g[lane], ga1 = ln_g[lane+32];
    float gb0 = ln_b[lane], gb1 = ln_b[lane+32];
    float bv0 = bwqkv[128+lane], bv1 = bwqkv[128+lane+32];
    int tok_base = blockIdx.x*64 + warp*8;
    int b = tok_base/NTOK;       // block never crosses batch (2304 % 64 == 0)
    for (int t = 0; t < 8; t++) {
        int token = tok_base + t;
        float x0 = x[token*64 + lane];
        float x1 = x[token*64 + lane + 32];
        float s = x0 + x1, ss = x0*x0 + x1*x1;
        #pragma unroll
        for (int off = 16; off; off >>= 1) {
            s  += __shfl_xor_sync(0xffffffffu, s,  off);
            ss += __shfl_xor_sync(0xffffffffu, ss, off);
        }
        float mu = s*(1.f/64.f);
        float var = ss*(1.f/64.f) - mu*mu;
        float rstd = rsqrtf(var + 1e-5f);
        float xn0 = (x0-mu)*rstd*ga0 + gb0;
        float xn1 = (x1-mu)*rstd*ga1 + gb1;
        g_xn[(size_t)token*64+lane] = xn0;
        g_xn[(size_t)token*64+lane+32] = xn1;
        sxb[warp*64+lane] = xn0; sxb[warp*64+lane+32] = xn1;
        __syncwarp();
        float v0 = bv0, v1 = bv1;
        #pragma unroll 8
        for (int d = 0; d < 64; d++) {
            float xd = sxb[warp*64+d];
            v0 += xd*swv[d*65+lane];
            v1 += xd*swv[d*65+lane+32];
        }
        int nn = token - b*NTOK;
        {
            int h0 = lane>>3, j0 = lane&7;
            g_v[((size_t)(b*8+h0)*NTOK + nn)*8 + j0] = v0;
            int h1 = (lane+32)>>3;
            g_v[((size_t)(b*8+h1)*NTOK + nn)*8 + j0] = v1;
        }
        if (lane < 8) {
            float a = g_bL[lane];
            #pragma unroll 8
            for (int d = 0; d < 64; d++) a += sxb[warp*64+d]*sWL[lane*65+d];
            g_logits[(b*8+lane)*NTOK + nn] = a;
        }
        __syncwarp();
    }
}

// ---------------- K2: per-(b,h) max ----------------
__global__ void k_max()
{
    __shared__ float red[256];
    int bid = blockIdx.x, tid = threadIdx.x;
    float m = -1e30f;
    for (int i = tid; i < NTOK; i += 256) m = fmaxf(m, g_logits[bid*NTOK + i]);
    red[tid] = m;
    __syncthreads();
    for (int s = 128; s; s >>= 1) {
        if (tid < s) red[tid] = fmaxf(red[tid], red[tid+s]);
        __syncthreads();
    }
    if (tid == 0) g_m[bid] = fmaxf(red[0], g_clslogit[bid&7]);
}

// ---------------- K3: exp + integral-image quad sums + cls_out ----------------
__global__ void __launch_bounds__(256) k_quad()
{
    extern __shared__ float s[];  // 9 * 2304 floats
    int bid = blockIdx.x, tid = threadIdx.x;
    int b = bid>>3, h = bid&7;
    float m = g_m[bid];
    float ecls = __expf(g_clslogit[h] - m);
    for (int p = tid; p < 2304; p += 256)
        s[p] = __expf(g_logits[bid*NTOK + p] - m);
    __syncthreads();
    const float* vbase = g_v + (size_t)bid*NTOK*8;
    for (int i = tid; i < 2304*8; i += 256) {
        int p = i>>3, j = i&7;
        s[(1+j)*2304 + p] = s[p] * vbase[i];
    }
    __syncthreads();
    for (int sid = tid; sid < 9*48; sid += 256) {
        int ch = sid/48, y = sid - (sid/48)*48;
        float* row = s + ch*2304 + y*48;
        float a = 0.f;
        for (int xx = 0; xx < 48; xx++) { a += row[xx]; row[xx] = a; }
    }
    __syncthreads();
    for (int sid = tid; sid < 9*48; sid += 256) {
        int ch = sid/48, xx = sid - (sid/48)*48;
        float* col = s + ch*2304 + xx;
        float a = 0.f;
        for (int y = 0; y < 48; y++) { a += col[y*48]; col[y*48] = a; }
    }
    __syncthreads();
    float vc[8];
    #pragma unroll
    for (int j = 0; j < 8; j++) vc[j] = g_vc[h*8+j];
    for (int p = tid; p < 2304; p += 256) {
        int y = p/48, xx = p - y*48;
        int iC  = p;
        int iRT = y*48 + 47;
        int iCB = 47*48 + xx;
        int iT  = 2303;
        int iCm = y*48 + xx - 1;
        int iUp = (y-1)*48 + xx;
        int iUR = (y-1)*48 + 47;
        int iCL = 47*48 + xx - 1;
        int iUL = (y-1)*48 + xx - 1;
        bool hx = xx > 0, hy = y > 0;
        float rd[4];
        {
            const float* C = s;
            float tl = C[iC];
            float tr = C[iRT] - (hx ? C[iCm] : 0.f);
            float bl = C[iCB] - (hy ? C[iUp] : 0.f);
            float br = C[iT] - (hy ? C[iUR] : 0.f) - (hx ? C[iCL] : 0.f) + ((hx&&hy) ? C[iUL] : 0.f);
            rd[0] = 1.f/(ecls+tl); rd[1] = 1.f/(ecls+tr);
            rd[2] = 1.f/(ecls+bl); rd[3] = 1.f/(ecls+br);
        }
        float out[4][8];
        #pragma unroll
        for (int j = 0; j < 8; j++) {
            const float* C = s + (1+j)*2304;
            float tl = C[iC];
            float tr = C[iRT] - (hx ? C[iCm] : 0.f);
            float bl = C[iCB] - (hy ? C[iUp] : 0.f);
            float br = C[iT] - (hy ? C[iUR] : 0.f) - (hx ? C[iCL] : 0.f) + ((hx&&hy) ? C[iUL] : 0.f);
            float base = ecls*vc[j];
            out[0][j] = (base+tl)*rd[0];
            out[1][j] = (base+tr)*rd[1];
            out[2][j] = (base+bl)*rd[2];
            out[3][j] = (base+br)*rd[3];
        }
        float* op = g_cls + ((size_t)(b*NTOK + p)*4)*64 + h*8;
        #pragma unroll
        for (int r = 0; r < 4; r++) {
            float4 v0 = make_float4(out[r][0], out[r][1], out[r][2], out[r][3]);
            float4 v1 = make_float4(out[r][4], out[r][5], out[r][6], out[r][7]);
            *(float4*)(op + r*64)     = v0;
            *(float4*)(op + r*64 + 4) = v1;
        }
    }
}

// ---------------- K4: fused epilogue (f32x2 + float4 weight loads) ----------------
#define XS 68
__global__ void __launch_bounds__(256) k_epi(float* __restrict__ outp)
{
    extern __shared__ float s[];
    float*  sxn   = s;               // [64 f][XS]
    float*  scmix = s + 64*XS;       // [64 e][XS]
    float4* wsP4  = (float4*)(s + 2*64*XS);   // [32 f2][32 lane]
    float4* wsQ4  = wsP4 + 1024;              // [32 e2][32 lane]
    int tid = threadIdx.x, warp = tid>>5, lane = tid&31;
    int tok0 = blockIdx.x*64;
    int tb = warp*8;

    for (int i = tid; i < 4096; i += 256) {
        int t = i>>6, d = i&63;
        sxn[d*XS + t] = g_xn[(size_t)(tok0+t)*64 + d];
    }

    ull accO[2][4];
    #pragma unroll
    for (int e = 0; e < 2; e++)
        #pragma unroll
        for (int pr = 0; pr < 4; pr++) accO[e][pr] = pack2(0.f, 0.f);

    for (int h = 0; h < 8; h++) {
        __syncthreads();
        for (int i = tid; i < 1024; i += 256) {
            wsP4[i] = g_P4p[h*1024 + i];
            wsQ4[i] = g_Q4p[h*1024 + i];
        }
        __syncthreads();

        // GEMV1: qp2[e] = sum_f xn[f]*P2[f,e] + u2[e]
        float u2a = g_u2[h*64 + lane];
        float u2b = g_u2[h*64 + lane + 32];
        ull aQ[2][4];
        #pragma unroll
        for (int pr = 0; pr < 4; pr++) { aQ[0][pr] = pack2(u2a,u2a); aQ[1][pr] = pack2(u2b,u2b); }
        #pragma unroll 8
        for (int f2 = 0; f2 < 32; f2++) {
            float4 w = wsP4[f2*32 + lane];
            ull pa0 = pack2(w.x, w.x);
            ull pa1 = pack2(w.y, w.y);
            ull pb0 = pack2(w.z, w.z);
            ull pb1 = pack2(w.w, w.w);
            const ulonglong2* xr0 = (const ulonglong2*)(sxn + (2*f2)*XS + tb);
            const ulonglong2* xr1 = (const ulonglong2*)(sxn + (2*f2+1)*XS + tb);
            ulonglong2 xa = xr0[0], xb = xr0[1];
            ulonglong2 xc = xr1[0], xd = xr1[1];
            ffma2(aQ[0][0], xa.x, pa0); ffma2(aQ[0][1], xa.y, pa0);
            ffma2(aQ[0][2], xb.x, pa0); ffma2(aQ[0][3], xb.y, pa0);
            ffma2(aQ[1][0], xa.x, pa1); ffma2(aQ[1][1], xa.y, pa1);
            ffma2(aQ[1][2], xb.x, pa1); ffma2(aQ[1][3], xb.y, pa1);
            ffma2(aQ[0][0], xc.x, pb0); ffma2(aQ[0][1], xc.y, pb0);
            ffma2(aQ[0][2], xd.x, pb0); ffma2(aQ[0][3], xd.y, pb0);
            ffma2(aQ[1][0], xc.x, pb1); ffma2(aQ[1][1], xc.y, pb1);
            ffma2(aQ[1][2], xd.x, pb1); ffma2(aQ[1][3], xd.y, pb1);
        }
        float q0[8], q1[8];
        #pragma unroll
        for (int pr = 0; pr < 4; pr++) {
            unpack2(aQ[0][pr], q0[2*pr], q0[2*pr+1]);
            unpack2(aQ[1][pr], q1[2*pr], q1[2*pr+1]);
        }

        // scores + softmax + cmix
        #pragma unroll
        for (int t = 0; t < 8; t++) {
            const float* cp = g_cls + (size_t)(tok0 + tb + t)*256 + lane;
            float c0r0 = cp[0],   c1r0 = cp[32];
            float c0r1 = cp[64],  c1r1 = cp[96];
            float c0r2 = cp[128], c1r2 = cp[160];
            float c0r3 = cp[192], c1r3 = cp[224];
            float sc0 = q0[t]*c0r0 + q1[t]*c1r0;
            float sc1 = q0[t]*c0r1 + q1[t]*c1r1;
            float sc2 = q0[t]*c0r2 + q1[t]*c1r2;
            float sc3 = q0[t]*c0r3 + q1[t]*c1r3;
            #pragma unroll
            for (int off = 16; off; off >>= 1) {
                sc0 += __shfl_xor_sync(0xffffffffu, sc0, off);
                sc1 += __shfl_xor_sync(0xffffffffu, sc1, off);
                sc2 += __shfl_xor_sync(0xffffffffu, sc2, off);
                sc3 += __shfl_xor_sync(0xffffffffu, sc3, off);
            }
            float mx = fmaxf(fmaxf(sc0,sc1), fmaxf(sc2,sc3));
            float e0 = __expf(sc0-mx), e1 = __expf(sc1-mx);
            float e2 = __expf(sc2-mx), e3 = __expf(sc3-mx);
            float inv = 1.f/(e0+e1+e2+e3);
            float a0 = e0*inv, a1 = e1*inv, a2 = e2*inv, a3 = e3*inv;
            scmix[lane*XS + tb + t]      = a0*c0r0 + a1*c0r1 + a2*c0r2 + a3*c0r3;
            scmix[(lane+32)*XS + tb + t] = a0*c1r0 + a1*c1r1 + a2*c1r2 + a3*c1r3;
        }
        __syncwarp();

        // GEMV2: out[o] += sum_e cmix[e]*Q2[e,o]
        #pragma unroll 8
        for (int e2 = 0; e2 < 32; e2++) {
            float4 w = wsQ4[e2*32 + lane];
            ull pa0 = pack2(w.x, w.x);
            ull pa1 = pack2(w.y, w.y);
            ull pb0 = pack2(w.z, w.z);
            ull pb1 = pack2(w.w, w.w);
            const ulonglong2* mr0 = (const ulonglong2*)(scmix + (2*e2)*XS + tb);
            const ulonglong2* mr1 = (const ulonglong2*)(scmix + (2*e2+1)*XS + tb);
            ulonglong2 ma = mr0[0], mb = mr0[1];
            ulonglong2 mc = mr1[0], md = mr1[1];
            ffma2(accO[0][0], ma.x, pa0); ffma2(accO[0][1], ma.y, pa0);
            ffma2(accO[0][2], mb.x, pa0); ffma2(accO[0][3], mb.y, pa0);
            ffma2(accO[1][0], ma.x, pa1); ffma2(accO[1][1], ma.y, pa1);
            ffma2(accO[1][2], mb.x, pa1); ffma2(accO[1][3], mb.y, pa1);
            ffma2(accO[0][0], mc.x, pb0); ffma2(accO[0][1], mc.y, pb0);
            ffma2(accO[0][2], md.x, pb0); ffma2(accO[0][3], md.y, pb0);
            ffma2(accO[1][0], mc.x, pb1); ffma2(accO[1][1], mc.y, pb1);
            ffma2(accO[1][2], md.x, pb1); ffma2(accO[1][3], md.y, pb1);
        }
    }

    float o0[8], o1[8];
    #pragma unroll
    for (int pr = 0; pr < 4; pr++) {
        unpack2(accO[0][pr], o0[2*pr], o0[2*pr+1]);
        unpack2(accO[1][pr], o1[2*pr], o1[2*pr+1]);
    }
    float c0 = g_cvec2[lane], c1 = g_cvec2[lane+32];
    #pragma unroll
    for (int t = 0; t < 8; t++) {
        outp[(size_t)(tok0+tb+t)*64 + lane]      = o0[t] + c0;
        outp[(size_t)(tok0+tb+t)*64 + lane + 32] = o1[t] + c1;
    }
}

// ---------------- launch ----------------
extern "C" void kernel_launch(void* const* d_in, const int* in_sizes, int n_in,
                              void* d_out, int out_size)
{
    const float* x      = (const float*)d_in[0];
    const float* ln_g   = (const float*)d_in[1];
    const float* ln_b   = (const float*)d_in[2];
    const float* Wqkv   = (const float*)d_in[3];
    const float* bqkv   = (const float*)d_in[4];
    const float* cls_t  = (const float*)d_in[5];
    const float* Wwqkv  = (const float*)d_in[6];
    const float* bwqkv  = (const float*)d_in[7];
    const float* Wwproj = (const float*)d_in[8];
    const float* bwproj = (const float*)d_in[9];
    const float* Wraq   = (const float*)d_in[10];
    const float* Wrak   = (const float*)d_in[11];
    const float* Wrav   = (const float*)d_in[12];
    const float* Wrao   = (const float*)d_in[13];
    const float* brao   = (const float*)d_in[14];
    const float* Wout   = (const float*)d_in[15];
    const float* bout   = (const float*)d_in[16];
    float* outp = (float*)d_out;

    int epi_smem = (2*64*XS)*4 + 2*1024*16;   // 34816 + 32768 = 67584 B
    cudaFuncSetAttribute(k_quad,   cudaFuncAttributeMaxDynamicSharedMemorySize, 9*2304*4);
    cudaFuncSetAttribute(k_epi,    cudaFuncAttributeMaxDynamicSharedMemorySize, epi_smem);
    cudaFuncSetAttribute(precompC, cudaFuncAttributeMaxDynamicSharedMemorySize, 3*4096*4);

    precompA<<<1, 256>>>(cls_t, Wwqkv, bwqkv, brao, Wout, bout);
    precompGR<<<32, 256>>>(Wraq, Wrak, Wrao, Wrav);
    precompB<<<16, 256>>>(Wqkv, Wout, bqkv);
    precompC<<<16, 256, 3*4096*4>>>(Wwproj);
    precompD<<<1, 512>>>(bwproj);
    k_ln<<<TOKENS/64, 256>>>(x, ln_g, ln_b, Wwqkv, bwqkv);
    k_max<<<BB*NHEADS, 256>>>();
    k_quad<<<BB*NHEADS, 256, 9*2304*4>>>();
    k_epi<<<TOKENS/64, 256, epi_smem>>>(outp);
}

// round 5
// speedup vs baseline: 1.7643x; 1.0363x over previous
#include <cuda_runtime.h>
#include <math.h>

#define BB 64
#define NTOK 2304
#define DD 64
#define NHEADS 8
#define TOKENS (BB*NTOK)   // 147456

// ---------------- scratch (device globals; no allocations) ----------------
__device__ float g_xn[TOKENS*DD];
__device__ float g_v[TOKENS*DD];                 // head-major: [(b*8+h)*2304 + p]*8 + j
__device__ float g_logits[BB*NHEADS*NTOK];
__device__ float g_cls[(size_t)TOKENS*4*DD];     // [tok][r][64e]
__device__ float g_WL[NHEADS*DD];
__device__ float g_bL[NHEADS];
__device__ float g_vc[DD];
__device__ float g_clslogit[NHEADS];
__device__ float g_cvec[DD];
__device__ float g_cvecp[NHEADS*DD];             // per-head bwproj fold
__device__ float4 g_P4p[NHEADS*1024];   // [h][f2][lane] = (P2[2f2][l],P2[2f2][l+32],P2[2f2+1][l],P2[2f2+1][l+32])
__device__ float4 g_Q4p[NHEADS*1024];   // [h][e2][lane] = (Q2[2e2][l],Q2[2e2][l+32],Q2[2e2+1][l],Q2[2e2+1][l+32])
__device__ float g_u2[NHEADS*DD];

__device__ __forceinline__ float kscale() { return 0.35355339059327373f; } // 8^-0.5

// ---------------- f32x2 helpers ----------------
typedef unsigned long long ull;
__device__ __forceinline__ ull pack2(float x, float y) {
    ull r; asm("mov.b64 %0, {%1,%2};" : "=l"(r) : "f"(x), "f"(y)); return r;
}
__device__ __forceinline__ void unpack2(ull v, float& x, float& y) {
    asm("mov.b64 {%0,%1}, %2;" : "=f"(x), "=f"(y) : "l"(v));
}
__device__ __forceinline__ void ffma2(ull& acc, ull a, ull b) {
    asm("fma.rn.f32x2 %0, %1, %2, %0;" : "+l"(acc) : "l"(a), "l"(b));
}

#define SBUF 4160   // padded 64x64 buffer (allows 65-stride layouts)

// ---------------- single precompute kernel: 17 blocks ----------------
__global__ void __launch_bounds__(256) precomp(
    const float* __restrict__ cls_tok,
    const float* __restrict__ Wwqkv, const float* __restrict__ bwqkv,
    const float* __restrict__ brao,
    const float* __restrict__ Wout, const float* __restrict__ bout,
    const float* __restrict__ Wraq, const float* __restrict__ Wrak,
    const float* __restrict__ Wrao, const float* __restrict__ Wrav,
    const float* __restrict__ Wqkv, const float* __restrict__ bqkv,
    const float* __restrict__ Wwproj, const float* __restrict__ bwproj)
{
    extern __shared__ float s[];
    float* s0 = s;
    float* s1 = s + SBUF;
    float* s2 = s + 2*SBUF;
    int bid = blockIdx.x, tid = threadIdx.x;

    if (bid == 0) {
        // cls token quantities + WL + cvec
        __shared__ float scq[192];
        __shared__ float sqc[64];
        __shared__ float sred[256];
        if (tid < 192) {
            float a = bwqkv[tid];
            for (int d = 0; d < 64; d++) a += Wwqkv[tid*64+d]*cls_tok[d];
            scq[tid] = a;
        }
        __syncthreads();
        if (tid < 64) { sqc[tid] = scq[tid]*kscale(); g_vc[tid] = scq[128+tid]; }
        __syncthreads();
        if (tid < 8) {
            float cl = 0.f, bl = 0.f;
            for (int j = 0; j < 8; j++) {
                cl += sqc[tid*8+j]*scq[64+tid*8+j];
                bl += sqc[tid*8+j]*bwqkv[64+tid*8+j];
            }
            g_clslogit[tid] = cl; g_bL[tid] = bl;
        }
        for (int i = tid; i < 512; i += 256) {
            int h = i>>6, d = i&63;
            float a = 0.f;
            for (int j = 0; j < 8; j++) a += sqc[h*8+j]*Wwqkv[(64+h*8+j)*64+d];
            g_WL[i] = a;
        }
        {
            int o = tid>>2, q = tid&3;
            float a = (q==0) ? bout[o] : 0.f;
            for (int k = q*128; k < q*128+128; k++) a += Wout[o*512+k]*brao[k&63];
            sred[tid] = a;
        }
        __syncthreads();
        if (tid < 64)
            g_cvec[tid] = sred[4*tid] + sred[4*tid+1] + sred[4*tid+2] + sred[4*tid+3];
    }
    else if (bid <= 8) {
        // ---- P side: G = Wraq^T Wrak ; P = scale*Wq_h^T G ; P2 = P Wwproj ----
        int h = bid - 1;
        __shared__ float su[64];
        for (int i = tid; i < 4096; i += 256) { s0[i] = Wraq[i]; s1[i] = Wrak[i]; }
        __syncthreads();
        for (int i = tid; i < 4096; i += 256) {           // G[dd][g] -> s2
            int dd = i>>6, g = i&63;
            float a = 0.f;
            #pragma unroll 8
            for (int e = 0; e < 64; e++) a += s0[e*64+dd]*s1[e*64+g];
            s2[i] = a;
        }
        __syncthreads();
        for (int i = tid; i < 4096; i += 256) s0[i] = Wqkv[h*4096 + i];   // Wq[dd][f]
        __syncthreads();
        for (int i = tid; i < 4096; i += 256) {           // P[f][g] -> s1
            int f = i>>6, g = i&63;
            float a = 0.f;
            #pragma unroll 8
            for (int dd = 0; dd < 64; dd++) a += s0[dd*64+f]*s2[dd*64+g];
            s1[i] = a*kscale();
        }
        if (tid < 64) {                                    // u[g]
            float a = 0.f;
            for (int dd = 0; dd < 64; dd++) a += bqkv[h*64+dd]*s2[dd*64+tid];
            su[tid] = a*kscale();
        }
        __syncthreads();
        for (int i = tid; i < 4096; i += 256) s0[i] = Wwproj[i];   // W[g][e]
        __syncthreads();
        for (int i = tid; i < 4096; i += 256) {           // P2[f][e] -> s2
            int f = i>>6, e = i&63;
            float a = 0.f;
            #pragma unroll 8
            for (int g = 0; g < 64; g++) a += s1[f*64+g]*s0[g*64+e];
            s2[i] = a;
        }
        if (tid < 64) {                                    // u2[e]
            float a = 0.f;
            for (int g = 0; g < 64; g++) a += su[g]*s0[g*64+tid];
            g_u2[h*64+tid] = a;
        }
        __syncthreads();
        for (int i = tid; i < 1024; i += 256) {            // pack
            int k2 = i>>5, l = i&31;
            g_P4p[h*1024+i] = make_float4(s2[(2*k2)*64+l],   s2[(2*k2)*64+l+32],
                                          s2[(2*k2+1)*64+l], s2[(2*k2+1)*64+l+32]);
        }
    }
    else {
        // ---- Q side: R = Wrao Wrav ; Q_h = Wout_h R ; Q2 = Wwproj^T Q ----
        int h = bid - 9;
        for (int i = tid; i < 4096; i += 256) { s0[i] = Wrao[i]; s1[i] = Wrav[i]; }
        __syncthreads();
        for (int i = tid; i < 4096; i += 256) {           // R[a][g] -> s2
            int a_ = i>>6, g = i&63;
            float a = 0.f;
            #pragma unroll 8
            for (int c = 0; c < 64; c++) a += s0[a_*64+c]*s1[c*64+g];
            s2[i] = a;
        }
        __syncthreads();
        for (int i = tid; i < 4096; i += 256) {           // Wout_h[o][a]
            int o = i>>6, a_ = i&63;
            s0[i] = Wout[o*512 + h*64 + a_];
        }
        __syncthreads();
        for (int i = tid; i < 4096; i += 256) {           // Qt[o][g] = Q[g][o] -> s1
            int o = i>>6, g = i&63;
            float a = 0.f;
            #pragma unroll 8
            for (int a_ = 0; a_ < 64; a_++) a += s0[o*64+a_]*s2[a_*64+g];
            s1[i] = a;
        }
        __syncthreads();
        if (tid < 64) {                                    // cvecp[h][o]
            float a = 0.f;
            for (int g = 0; g < 64; g++) a += bwproj[g]*s1[tid*64+g];
            g_cvecp[h*64+tid] = a;
        }
        for (int i = tid; i < 4096; i += 256) s0[i] = Wwproj[i];   // W[g][e]
        __syncthreads();
        for (int i = tid; i < 4096; i += 256) {           // Q2t[o][e] -> s2 (65-stride)
            int o = i>>6, e = i&63;
            float a = 0.f;
            #pragma unroll 8
            for (int g = 0; g < 64; g++) a += s0[g*64+e]*s1[o*64+g];
            s2[o*65+e] = a;
        }
        __syncthreads();
        for (int i = tid; i < 1024; i += 256) {            // pack: Q2[e][o] = s2[o*65+e]
            int k2 = i>>5, l = i&31;
            g_Q4p[h*1024+i] = make_float4(s2[l*65 + 2*k2],      s2[(l+32)*65 + 2*k2],
                                          s2[l*65 + 2*k2 + 1],  s2[(l+32)*65 + 2*k2 + 1]);
        }
    }
}

// ---------------- K1: LayerNorm + logits + v projection (64 tokens/block) ----------------
__global__ void __launch_bounds__(256) k_ln(const float* __restrict__ x,
     const float* __restrict__ ln_g, const float* __restrict__ ln_b,
     const float* __restrict__ Wwqkv, const float* __restrict__ bwqkv)
{
    __shared__ float sfv[64*66];     // pairs (Wwv[e][d], Wwv[e+32][d]) at [d*66 + 2*(e&31) + (e>>5)]
    __shared__ float sWL[8*65];
    __shared__ float sxb[8*64];
    int tid = threadIdx.x, warp = tid>>5, lane = tid&31;
    for (int i = tid; i < 4096; i += 256) {
        int e = i>>6, d = i&63;
        sfv[d*66 + 2*(e&31) + (e>>5)] = Wwqkv[8192 + i];
    }
    for (int i = tid; i < 512; i += 256)
        sWL[(i>>6)*65 + (i&63)] = g_WL[i];
    __syncthreads();
    float ga0 = ln_g[lane], ga1 = ln_g[lane+32];
    float gb0 = ln_b[lane], gb1 = ln_b[lane+32];
    float bv0 = bwqkv[128+lane], bv1 = bwqkv[128+lane+32];
    int tok_base = blockIdx.x*64 + warp*8;
    int b = tok_base/NTOK;
    int hh = lane>>2, qq = lane&3;
    for (int t = 0; t < 8; t++) {
        int token = tok_base + t;
        float x0 = x[token*64 + lane];
        float x1 = x[token*64 + lane + 32];
        float s = x0 + x1, ss = x0*x0 + x1*x1;
        #pragma unroll
        for (int off = 16; off; off >>= 1) {
            s  += __shfl_xor_sync(0xffffffffu, s,  off);
            ss += __shfl_xor_sync(0xffffffffu, ss, off);
        }
        float mu = s*(1.f/64.f);
        float var = ss*(1.f/64.f) - mu*mu;
        float rstd = rsqrtf(var + 1e-5f);
        float xn0 = (x0-mu)*rstd*ga0 + gb0;
        float xn1 = (x1-mu)*rstd*ga1 + gb1;
        g_xn[(size_t)token*64+lane] = xn0;
        g_xn[(size_t)token*64+lane+32] = xn1;
        sxb[warp*64+lane] = xn0; sxb[warp*64+lane+32] = xn1;
        __syncwarp();
        // v projection via f32x2
        ull acc = pack2(bv0, bv1);
        #pragma unroll 8
        for (int d = 0; d < 64; d++) {
            float xd = sxb[warp*64+d];
            float2 w = *(const float2*)(sfv + d*66 + 2*lane);
            ffma2(acc, pack2(xd, xd), pack2(w.x, w.y));
        }
        float v0, v1; unpack2(acc, v0, v1);
        int nn = token - b*NTOK;
        {
            int h0 = lane>>3, j0 = lane&7;
            g_v[((size_t)(b*8+h0)*NTOK + nn)*8 + j0] = v0;
            int h1 = (lane+32)>>3;
            g_v[((size_t)(b*8+h1)*NTOK + nn)*8 + j0] = v1;
        }
        // logits: 4 lanes per head
        {
            float a = 0.f;
            #pragma unroll
            for (int dd = 0; dd < 16; dd++)
                a += sxb[warp*64 + qq*16 + dd]*sWL[hh*65 + qq*16 + dd];
            a += __shfl_xor_sync(0xffffffffu, a, 1);
            a += __shfl_xor_sync(0xffffffffu, a, 2);
            if (qq == 0) g_logits[(b*8+hh)*NTOK + nn] = a + g_bL[hh];
        }
        __syncwarp();
    }
}

// ---------------- K2: max + exp + integral-image quad sums + cls_out ----------------
__global__ void __launch_bounds__(256) k_quad()
{
    extern __shared__ float s[];  // 9 * 2304 floats
    __shared__ float red[256];
    __shared__ float smv;
    int bid = blockIdx.x, tid = threadIdx.x;
    int b = bid>>3, h = bid&7;
    for (int p = tid; p < 2304; p += 256)
        s[p] = g_logits[bid*NTOK + p];
    __syncthreads();
    float mloc = -1e30f;
    for (int p = tid; p < 2304; p += 256) mloc = fmaxf(mloc, s[p]);
    red[tid] = mloc;
    __syncthreads();
    for (int st = 128; st; st >>= 1) {
        if (tid < st) red[tid] = fmaxf(red[tid], red[tid+st]);
        __syncthreads();
    }
    if (tid == 0) smv = fmaxf(red[0], g_clslogit[h]);
    __syncthreads();
    float m = smv;
    float ecls = __expf(g_clslogit[h] - m);
    for (int p = tid; p < 2304; p += 256)
        s[p] = __expf(s[p] - m);
    __syncthreads();
    const float* vbase = g_v + (size_t)bid*NTOK*8;
    for (int i = tid; i < 2304*8; i += 256) {
        int p = i>>3, j = i&7;
        s[(1+j)*2304 + p] = s[p] * vbase[i];
    }
    __syncthreads();
    for (int sid = tid; sid < 9*48; sid += 256) {
        int ch = sid/48, y = sid - (sid/48)*48;
        float* row = s + ch*2304 + y*48;
        float a = 0.f;
        for (int xx = 0; xx < 48; xx++) { a += row[xx]; row[xx] = a; }
    }
    __syncthreads();
    for (int sid = tid; sid < 9*48; sid += 256) {
        int ch = sid/48, xx = sid - (sid/48)*48;
        float* col = s + ch*2304 + xx;
        float a = 0.f;
        for (int y = 0; y < 48; y++) { a += col[y*48]; col[y*48] = a; }
    }
    __syncthreads();
    float vc[8];
    #pragma unroll
    for (int j = 0; j < 8; j++) vc[j] = g_vc[h*8+j];
    for (int p = tid; p < 2304; p += 256) {
        int y = p/48, xx = p - y*48;
        int iC  = p;
        int iRT = y*48 + 47;
        int iCB = 47*48 + xx;
        int iT  = 2303;
        int iCm = y*48 + xx - 1;
        int iUp = (y-1)*48 + xx;
        int iUR = (y-1)*48 + 47;
        int iCL = 47*48 + xx - 1;
        int iUL = (y-1)*48 + xx - 1;
        bool hx = xx > 0, hy = y > 0;
        float rd[4];
        {
            const float* C = s;
            float tl = C[iC];
            float tr = C[iRT] - (hx ? C[iCm] : 0.f);
            float bl = C[iCB] - (hy ? C[iUp] : 0.f);
            float br = C[iT] - (hy ? C[iUR] : 0.f) - (hx ? C[iCL] : 0.f) + ((hx&&hy) ? C[iUL] : 0.f);
            rd[0] = 1.f/(ecls+tl); rd[1] = 1.f/(ecls+tr);
            rd[2] = 1.f/(ecls+bl); rd[3] = 1.f/(ecls+br);
        }
        float out[4][8];
        #pragma unroll
        for (int j = 0; j < 8; j++) {
            const float* C = s + (1+j)*2304;
            float tl = C[iC];
            float tr = C[iRT] - (hx ? C[iCm] : 0.f);
            float bl = C[iCB] - (hy ? C[iUp] : 0.f);
            float br = C[iT] - (hy ? C[iUR] : 0.f) - (hx ? C[iCL] : 0.f) + ((hx&&hy) ? C[iUL] : 0.f);
            float base = ecls*vc[j];
            out[0][j] = (base+tl)*rd[0];
            out[1][j] = (base+tr)*rd[1];
            out[2][j] = (base+bl)*rd[2];
            out[3][j] = (base+br)*rd[3];
        }
        float* op = g_cls + ((size_t)(b*NTOK + p)*4)*64 + h*8;
        #pragma unroll
        for (int r = 0; r < 4; r++) {
            float4 v0 = make_float4(out[r][0], out[r][1], out[r][2], out[r][3]);
            float4 v1 = make_float4(out[r][4], out[r][5], out[r][6], out[r][7]);
            *(float4*)(op + r*64)     = v0;
            *(float4*)(op + r*64 + 4) = v1;
        }
    }
}

// ---------------- K3: fused epilogue (f32x2 + float4 weight loads) ----------------
#define XS 68
__global__ void __launch_bounds__(256) k_epi(float* __restrict__ outp)
{
    extern __shared__ float s[];
    float*  sxn   = s;               // [64 f][XS]
    float*  scmix = s + 64*XS;       // [64 e][XS]
    float4* wsP4  = (float4*)(s + 2*64*XS);   // [32 f2][32 lane]
    float4* wsQ4  = wsP4 + 1024;              // [32 e2][32 lane]
    __shared__ float scv[64];
    int tid = threadIdx.x, warp = tid>>5, lane = tid&31;
    int tok0 = blockIdx.x*64;
    int tb = warp*8;

    if (tid < 64) {
        float a = g_cvec[tid];
        #pragma unroll
        for (int h = 0; h < 8; h++) a += g_cvecp[h*64+tid];
        scv[tid] = a;
    }
    for (int i = tid; i < 4096; i += 256) {
        int t = i>>6, d = i&63;
        sxn[d*XS + t] = g_xn[(size_t)(tok0+t)*64 + d];
    }

    ull accO[2][4];
    #pragma unroll
    for (int e = 0; e < 2; e++)
        #pragma unroll
        for (int pr = 0; pr < 4; pr++) accO[e][pr] = pack2(0.f, 0.f);

    for (int h = 0; h < 8; h++) {
        __syncthreads();
        for (int i = tid; i < 1024; i += 256) {
            wsP4[i] = g_P4p[h*1024 + i];
            wsQ4[i] = g_Q4p[h*1024 + i];
        }
        __syncthreads();

        // GEMV1: qp2[e] = sum_f xn[f]*P2[f,e] + u2[e]
        float u2a = g_u2[h*64 + lane];
        float u2b = g_u2[h*64 + lane + 32];
        ull aQ[2][4];
        #pragma unroll
        for (int pr = 0; pr < 4; pr++) { aQ[0][pr] = pack2(u2a,u2a); aQ[1][pr] = pack2(u2b,u2b); }
        #pragma unroll 8
        for (int f2 = 0; f2 < 32; f2++) {
            float4 w = wsP4[f2*32 + lane];
            ull pa0 = pack2(w.x, w.x);
            ull pa1 = pack2(w.y, w.y);
            ull pb0 = pack2(w.z, w.z);
            ull pb1 = pack2(w.w, w.w);
            const ulonglong2* xr0 = (const ulonglong2*)(sxn + (2*f2)*XS + tb);
            const ulonglong2* xr1 = (const ulonglong2*)(sxn + (2*f2+1)*XS + tb);
            ulonglong2 xa = xr0[0], xb = xr0[1];
            ulonglong2 xc = xr1[0], xd = xr1[1];
            ffma2(aQ[0][0], xa.x, pa0); ffma2(aQ[0][1], xa.y, pa0);
            ffma2(aQ[0][2], xb.x, pa0); ffma2(aQ[0][3], xb.y, pa0);
            ffma2(aQ[1][0], xa.x, pa1); ffma2(aQ[1][1], xa.y, pa1);
            ffma2(aQ[1][2], xb.x, pa1); ffma2(aQ[1][3], xb.y, pa1);
            ffma2(aQ[0][0], xc.x, pb0); ffma2(aQ[0][1], xc.y, pb0);
            ffma2(aQ[0][2], xd.x, pb0); ffma2(aQ[0][3], xd.y, pb0);
            ffma2(aQ[1][0], xc.x, pb1); ffma2(aQ[1][1], xc.y, pb1);
            ffma2(aQ[1][2], xd.x, pb1); ffma2(aQ[1][3], xd.y, pb1);
        }
        float q0[8], q1[8];
        #pragma unroll
        for (int pr = 0; pr < 4; pr++) {
            unpack2(aQ[0][pr], q0[2*pr], q0[2*pr+1]);
            unpack2(aQ[1][pr], q1[2*pr], q1[2*pr+1]);
        }

        // scores + softmax + cmix
        #pragma unroll
        for (int t = 0; t < 8; t++) {
            const float* cp = g_cls + (size_t)(tok0 + tb + t)*256 + lane;
            float c0r0 = cp[0],   c1r0 = cp[32];
            float c0r1 = cp[64],  c1r1 = cp[96];
            float c0r2 = cp[128], c1r2 = cp[160];
            float c0r3 = cp[192], c1r3 = cp[224];
            float sc0 = q0[t]*c0r0 + q1[t]*c1r0;
            float sc1 = q0[t]*c0r1 + q1[t]*c1r1;
            float sc2 = q0[t]*c0r2 + q1[t]*c1r2;
            float sc3 = q0[t]*c0r3 + q1[t]*c1r3;
            #pragma unroll
            for (int off = 16; off; off >>= 1) {
                sc0 += __shfl_xor_sync(0xffffffffu, sc0, off);
                sc1 += __shfl_xor_sync(0xffffffffu, sc1, off);
                sc2 += __shfl_xor_sync(0xffffffffu, sc2, off);
                sc3 += __shfl_xor_sync(0xffffffffu, sc3, off);
            }
            float mx = fmaxf(fmaxf(sc0,sc1), fmaxf(sc2,sc3));
            float e0 = __expf(sc0-mx), e1 = __expf(sc1-mx);
            float e2 = __expf(sc2-mx), e3 = __expf(sc3-mx);
            float inv = 1.f/(e0+e1+e2+e3);
            float a0 = e0*inv, a1 = e1*inv, a2 = e2*inv, a3 = e3*inv;
            scmix[lane*XS + tb + t]      = a0*c0r0 + a1*c0r1 + a2*c0r2 + a3*c0r3;
            scmix[(lane+32)*XS + tb + t] = a0*c1r0 + a1*c1r1 + a2*c1r2 + a3*c1r3;
        }
        __syncwarp();

        // GEMV2: out[o] += sum_e cmix[e]*Q2[e,o]
        #pragma unroll 8
        for (int e2 = 0; e2 < 32; e2++) {
            float4 w = wsQ4[e2*32 + lane];
            ull pa0 = pack2(w.x, w.x);
            ull pa1 = pack2(w.y, w.y);
            ull pb0 = pack2(w.z, w.z);
            ull pb1 = pack2(w.w, w.w);
            const ulonglong2* mr0 = (const ulonglong2*)(scmix + (2*e2)*XS + tb);
            const ulonglong2* mr1 = (const ulonglong2*)(scmix + (2*e2+1)*XS + tb);
            ulonglong2 ma = mr0[0], mb = mr0[1];
            ulonglong2 mc = mr1[0], md = mr1[1];
            ffma2(accO[0][0], ma.x, pa0); ffma2(accO[0][1], ma.y, pa0);
            ffma2(accO[0][2], mb.x, pa0); ffma2(accO[0][3], mb.y, pa0);
            ffma2(accO[1][0], ma.x, pa1); ffma2(accO[1][1], ma.y, pa1);
            ffma2(accO[1][2], mb.x, pa1); ffma2(accO[1][3], mb.y, pa1);
            ffma2(accO[0][0], mc.x, pb0); ffma2(accO[0][1], mc.y, pb0);
            ffma2(accO[0][2], md.x, pb0); ffma2(accO[0][3], md.y, pb0);
            ffma2(accO[1][0], mc.x, pb1); ffma2(accO[1][1], mc.y, pb1);
            ffma2(accO[1][2], md.x, pb1); ffma2(accO[1][3], md.y, pb1);
        }
    }

    float o0[8], o1[8];
    #pragma unroll
    for (int pr = 0; pr < 4; pr++) {
        unpack2(accO[0][pr], o0[2*pr], o0[2*pr+1]);
        unpack2(accO[1][pr], o1[2*pr], o1[2*pr+1]);
    }
    float c0 = scv[lane], c1 = scv[lane+32];
    #pragma unroll
    for (int t = 0; t < 8; t++) {
        outp[(size_t)(tok0+tb+t)*64 + lane]      = o0[t] + c0;
        outp[(size_t)(tok0+tb+t)*64 + lane + 32] = o1[t] + c1;
    }
}

// ---------------- launch ----------------
extern "C" void kernel_launch(void* const* d_in, const int* in_sizes, int n_in,
                              void* d_out, int out_size)
{
    const float* x      = (const float*)d_in[0];
    const float* ln_g   = (const float*)d_in[1];
    const float* ln_b   = (const float*)d_in[2];
    const float* Wqkv   = (const float*)d_in[3];
    const float* bqkv   = (const float*)d_in[4];
    const float* cls_t  = (const float*)d_in[5];
    const float* Wwqkv  = (const float*)d_in[6];
    const float* bwqkv  = (const float*)d_in[7];
    const float* Wwproj = (const float*)d_in[8];
    const float* bwproj = (const float*)d_in[9];
    const float* Wraq   = (const float*)d_in[10];
    const float* Wrak   = (const float*)d_in[11];
    const float* Wrav   = (const float*)d_in[12];
    const float* Wrao   = (const float*)d_in[13];
    const float* brao   = (const float*)d_in[14];
    const float* Wout   = (const float*)d_in[15];
    const float* bout   = (const float*)d_in[16];
    float* outp = (float*)d_out;

    int pre_smem = 3*SBUF*4;                  // 49920 B
    int epi_smem = (2*64*XS)*4 + 2*1024*16;   // 67584 B
    cudaFuncSetAttribute(precomp, cudaFuncAttributeMaxDynamicSharedMemorySize, pre_smem);
    cudaFuncSetAttribute(k_quad,  cudaFuncAttributeMaxDynamicSharedMemorySize, 9*2304*4);
    cudaFuncSetAttribute(k_epi,   cudaFuncAttributeMaxDynamicSharedMemorySize, epi_smem);

    precomp<<<17, 256, pre_smem>>>(cls_t, Wwqkv, bwqkv, brao, Wout, bout,
                                   Wraq, Wrak, Wrao, Wrav, Wqkv, bqkv, Wwproj, bwproj);
    k_ln<<<TOKENS/64, 256>>>(x, ln_g, ln_b, Wwqkv, bwqkv);
    k_quad<<<BB*NHEADS, 256, 9*2304*4>>>();
    k_epi<<<TOKENS/64, 256, epi_smem>>>(outp);
}